// round 4
// baseline (speedup 1.0000x reference)
#include <cuda_runtime.h>
#include <cuda_bf16.h>
#include <cstdint>

#define N_NODES 50000
#define N_EDGES 800000
#define IN_DIM  128
#define HID_DIM 128
#define OUT_DIM 64

// ---------------- scratch (device globals: no allocation allowed) -------------
// 16B alignment: targets of LDG.128 / 128-bit atomicAdd.
__device__ __align__(16) float g_deg [N_NODES];
__device__ __align__(16) float g_dinv[N_NODES];
__device__ __align__(16) float g_xw  [N_NODES * HID_DIM];   // x @ W1
__device__ __align__(16) float g_agg1[N_NODES * HID_DIM];   // scatter target layer 1
__device__ __align__(16) float g_h   [N_NODES * HID_DIM];   // relu(agg1 + self + b1)
__device__ __align__(16) float g_hw  [N_NODES * OUT_DIM];   // h @ W2
__device__ __align__(16) float g_agg2[N_NODES * OUT_DIM];   // scatter target layer 2

// ---------------- zero scratch -------------------------------------------------
__global__ void zero_kernel() {
    int i = blockIdx.x * blockDim.x + threadIdx.x;
    int stride = gridDim.x * blockDim.x;
    float4* a1 = reinterpret_cast<float4*>(g_agg1);
    float4* a2 = reinterpret_cast<float4*>(g_agg2);
    const int n1 = N_NODES * HID_DIM / 4;
    const int n2 = N_NODES * OUT_DIM / 4;
    float4 z = make_float4(0.f, 0.f, 0.f, 0.f);
    for (int j = i; j < n1; j += stride) a1[j] = z;
    for (int j = i; j < n2; j += stride) a2[j] = z;
    for (int j = i; j < N_NODES; j += stride) g_deg[j] = 0.f;
}

// ---------------- degree + dinv ------------------------------------------------
__global__ void deg_kernel(const int* __restrict__ dst) {
    int e = blockIdx.x * blockDim.x + threadIdx.x;
    if (e >= N_EDGES) return;
    unsigned d = (unsigned)dst[e];
    if (d < N_NODES) atomicAdd(&g_deg[d], 1.0f);
}

__global__ void dinv_kernel() {
    int i = blockIdx.x * blockDim.x + threadIdx.x;
    if (i < N_NODES) g_dinv[i] = rsqrtf(g_deg[i] + 1.0f);
}

// ---------------- SGEMM: C[M,NDIM] = A[M,128] @ B[128,NDIM] --------------------
template <int NDIM>
__device__ __forceinline__ void sgemm_body(const float* __restrict__ A,
                                           const float* __restrict__ B,
                                           float* __restrict__ C, int M) {
    constexpr int BM = 64, BN = 64, BK = 32, KDIM = 128;
    __shared__ float As[BM][BK];
    __shared__ float Bs[BK][BN];

    const int tid = threadIdx.x;          // 256 threads
    const int tx = tid & 15;              // 0..15 -> 4 cols each
    const int ty = tid >> 4;              // 0..15 -> 4 rows each
    const int row0 = blockIdx.y * BM;
    const int col0 = blockIdx.x * BN;

    float acc[4][4] = {};

    for (int k0 = 0; k0 < KDIM; k0 += BK) {
        #pragma unroll
        for (int l = 0; l < 8; l++) {     // 2048 A elems / 256 threads
            int idx = tid + l * 256;
            int m = idx >> 5, k = idx & 31;
            int r = row0 + m;
            As[m][k] = (r < M) ? A[(size_t)r * KDIM + k0 + k] : 0.f;
        }
        #pragma unroll
        for (int l = 0; l < 8; l++) {     // 2048 B elems
            int idx = tid + l * 256;
            int k = idx >> 6, n = idx & 63;
            Bs[k][n] = B[(size_t)(k0 + k) * NDIM + col0 + n];
        }
        __syncthreads();

        #pragma unroll
        for (int k = 0; k < BK; k++) {
            float a0 = As[ty * 4 + 0][k];
            float a1 = As[ty * 4 + 1][k];
            float a2 = As[ty * 4 + 2][k];
            float a3 = As[ty * 4 + 3][k];
            float4 b = *reinterpret_cast<const float4*>(&Bs[k][tx * 4]);
            acc[0][0] += a0 * b.x; acc[0][1] += a0 * b.y; acc[0][2] += a0 * b.z; acc[0][3] += a0 * b.w;
            acc[1][0] += a1 * b.x; acc[1][1] += a1 * b.y; acc[1][2] += a1 * b.z; acc[1][3] += a1 * b.w;
            acc[2][0] += a2 * b.x; acc[2][1] += a2 * b.y; acc[2][2] += a2 * b.z; acc[2][3] += a2 * b.w;
            acc[3][0] += a3 * b.x; acc[3][1] += a3 * b.y; acc[3][2] += a3 * b.z; acc[3][3] += a3 * b.w;
        }
        __syncthreads();
    }

    #pragma unroll
    for (int i = 0; i < 4; i++) {
        int r = row0 + ty * 4 + i;
        if (r < M) {
            float4 v = make_float4(acc[i][0], acc[i][1], acc[i][2], acc[i][3]);
            *reinterpret_cast<float4*>(&C[(size_t)r * NDIM + col0 + tx * 4]) = v;
        }
    }
}

__global__ void gemm1_kernel(const float* __restrict__ A, const float* __restrict__ B) {
    sgemm_body<HID_DIM>(A, B, g_xw, N_NODES);
}
__global__ void gemm2_kernel(const float* __restrict__ B) {
    sgemm_body<OUT_DIM>(g_h, B, g_hw, N_NODES);
}

// ---------------- edge scatter layer 1: one warp per edge, 128 floats ----------
__global__ void scatter1_kernel(const int* __restrict__ src,
                                const int* __restrict__ dst) {
    int warp = (blockIdx.x * blockDim.x + threadIdx.x) >> 5;
    int lane = threadIdx.x & 31;
    if (warp >= N_EDGES) return;
    unsigned s = (unsigned)__ldg(&src[warp]);
    unsigned d = (unsigned)__ldg(&dst[warp]);
    if (s >= N_NODES || d >= N_NODES) return;   // guard (also dtype insurance)
    float norm = g_dinv[s] * g_dinv[d];
    const float4* xs = reinterpret_cast<const float4*>(g_xw + (size_t)s * HID_DIM);
    float4 v = xs[lane];
    v.x *= norm; v.y *= norm; v.z *= norm; v.w *= norm;
    // native 128-bit float4 atomic add (sm_90+ intrinsic; no-return RED form)
    atomicAdd(reinterpret_cast<float4*>(g_agg1 + (size_t)d * HID_DIM) + lane, v);
}

// ---------------- edge scatter layer 2: 16 threads per edge, 64 floats ---------
__global__ void scatter2_kernel(const int* __restrict__ src,
                                const int* __restrict__ dst) {
    int idx = blockIdx.x * blockDim.x + threadIdx.x;
    int e = idx >> 4;
    int j = idx & 15;
    if (e >= N_EDGES) return;
    unsigned s = (unsigned)__ldg(&src[e]);
    unsigned d = (unsigned)__ldg(&dst[e]);
    if (s >= N_NODES || d >= N_NODES) return;
    float norm = g_dinv[s] * g_dinv[d];
    const float4* hs = reinterpret_cast<const float4*>(g_hw + (size_t)s * OUT_DIM);
    float4 v = hs[j];
    v.x *= norm; v.y *= norm; v.z *= norm; v.w *= norm;
    atomicAdd(reinterpret_cast<float4*>(g_agg2 + (size_t)d * OUT_DIM) + j, v);
}

// ---------------- layer-1 epilogue: h = relu(agg1 + xw*dinv^2 + b1) ------------
__global__ void selfloop1_kernel(const float* __restrict__ b1) {
    int idx = blockIdx.x * blockDim.x + threadIdx.x;    // float4 index
    const int total = N_NODES * HID_DIM / 4;            // 32 float4 per node
    if (idx >= total) return;
    int node = idx >> 5;
    int c4 = idx & 31;
    float di = g_dinv[node];
    float w = di * di;
    float4 a  = reinterpret_cast<const float4*>(g_agg1)[idx];
    float4 xw = reinterpret_cast<const float4*>(g_xw)[idx];
    float4 bb = reinterpret_cast<const float4*>(b1)[c4];
    float4 r;
    r.x = fmaxf(a.x + xw.x * w + bb.x, 0.f);
    r.y = fmaxf(a.y + xw.y * w + bb.y, 0.f);
    r.z = fmaxf(a.z + xw.z * w + bb.z, 0.f);
    r.w = fmaxf(a.w + xw.w * w + bb.w, 0.f);
    reinterpret_cast<float4*>(g_h)[idx] = r;
}

// ---------------- final: out = leaky_relu((agg2 + hw*dinv^2 + b2) @ Wfc + bfc) -
__global__ void final_kernel(const float* __restrict__ b2,
                             const float* __restrict__ Wfc,
                             const float* __restrict__ bfc,
                             float* __restrict__ out) {
    int node = (blockIdx.x * blockDim.x + threadIdx.x) >> 5;
    int lane = threadIdx.x & 31;
    if (node >= N_NODES) return;
    float di = g_dinv[node];
    float w = di * di;
    int c0 = 2 * lane, c1 = 2 * lane + 1;
    size_t base = (size_t)node * OUT_DIM;
    float v0 = g_agg2[base + c0] + g_hw[base + c0] * w + b2[c0];
    float v1 = g_agg2[base + c1] + g_hw[base + c1] * w + b2[c1];
    float p0 = v0 * Wfc[c0 * 2 + 0] + v1 * Wfc[c1 * 2 + 0];
    float p1 = v0 * Wfc[c0 * 2 + 1] + v1 * Wfc[c1 * 2 + 1];
    #pragma unroll
    for (int off = 16; off > 0; off >>= 1) {
        p0 += __shfl_xor_sync(0xffffffff, p0, off);
        p1 += __shfl_xor_sync(0xffffffff, p1, off);
    }
    if (lane == 0) {
        float o0 = p0 + bfc[0];
        float o1 = p1 + bfc[1];
        out[node * 2 + 0] = (o0 > 0.f) ? o0 : 0.01f * o0;
        out[node * 2 + 1] = (o1 > 0.f) ? o1 : 0.01f * o1;
    }
}

// ---------------- launch -------------------------------------------------------
extern "C" void kernel_launch(void* const* d_in, const int* in_sizes, int n_in,
                              void* d_out, int out_size) {
    const float* x   = (const float*)d_in[0];
    const int*   ei  = (const int*)d_in[1];   // JAX demotes int64 -> int32 (x64 off)
    const float* W1  = (const float*)d_in[2];
    const float* b1  = (const float*)d_in[3];
    const float* W2  = (const float*)d_in[4];
    const float* b2  = (const float*)d_in[5];
    const float* Wfc = (const float*)d_in[6];
    const float* bfc = (const float*)d_in[7];
    float* out = (float*)d_out;

    const int* src = ei;
    const int* dst = ei + N_EDGES;

    zero_kernel<<<1184, 256>>>();
    deg_kernel<<<(N_EDGES + 255) / 256, 256>>>(dst);
    dinv_kernel<<<(N_NODES + 255) / 256, 256>>>();

    // layer 1
    gemm1_kernel<<<dim3(HID_DIM / 64, (N_NODES + 63) / 64), 256>>>(x, W1);
    scatter1_kernel<<<(N_EDGES * 32 + 255) / 256, 256>>>(src, dst);
    selfloop1_kernel<<<(N_NODES * HID_DIM / 4 + 255) / 256, 256>>>(b1);

    // layer 2
    gemm2_kernel<<<dim3(OUT_DIM / 64, (N_NODES + 63) / 64), 256>>>(W2);
    scatter2_kernel<<<(N_EDGES * 16 + 255) / 256, 256>>>(src, dst);

    // fc + leaky relu
    final_kernel<<<(N_NODES * 32 + 255) / 256, 256>>>(b2, Wfc, bfc, out);
}

// round 6
// speedup vs baseline: 1.6555x; 1.6555x over previous
#include <cuda_runtime.h>
#include <cuda_bf16.h>
#include <cstdint>

#define N_NODES 50000
#define N_EDGES 800000
#define IN_DIM  128
#define HID_DIM 128
#define OUT_DIM 64

#define SCAN_BS   512
#define SCAN_NB   ((N_NODES + SCAN_BS - 1) / SCAN_BS)   // 98

// ---------------- scratch (device globals: no allocation allowed) -------------
// NOTE: only ever referenced from DEVICE code (host-side use of __device__
// symbols yields the host shadow address -> silent ATS writes to host RAM).
__device__ __align__(16) int   g_degi    [N_NODES];
__device__ __align__(16) float g_dinv    [N_NODES];
__device__ __align__(16) int   g_rowstart[N_NODES + 1];
__device__ __align__(16) int   g_pos     [N_NODES];
__device__ __align__(16) int   g_csr     [N_EDGES];        // src node per CSR slot
__device__ __align__(16) int   g_bsum    [SCAN_NB];
__device__ __align__(16) int   g_bsumx   [SCAN_NB];
__device__ __align__(16) float g_xw      [N_NODES * HID_DIM];  // (x@W1)*dinv[row]
__device__ __align__(16) float g_h       [N_NODES * HID_DIM];  // layer-1 output
__device__ __align__(16) float g_hw      [N_NODES * OUT_DIM];  // (h@W2)*dinv[row]

// ---------------- degree -------------------------------------------------------
__global__ void zero_deg_kernel() {
    int i = blockIdx.x * blockDim.x + threadIdx.x;
    if (i < N_NODES) g_degi[i] = 0;
}

__global__ void deg_kernel(const int* __restrict__ dst) {
    int e = blockIdx.x * blockDim.x + threadIdx.x;
    if (e >= N_EDGES) return;
    unsigned d = (unsigned)dst[e];
    if (d < N_NODES) atomicAdd(&g_degi[d], 1);
}

__global__ void dinv_kernel() {
    int i = blockIdx.x * blockDim.x + threadIdx.x;
    if (i < N_NODES) g_dinv[i] = rsqrtf((float)g_degi[i] + 1.0f);
}

// ---------------- exclusive scan of degrees (3 kernels) ------------------------
__global__ void scanA_kernel() {
    __shared__ int sm[SCAN_BS];
    int t = threadIdx.x;
    int i = blockIdx.x * SCAN_BS + t;
    int s = (i < N_NODES) ? g_degi[i] : 0;
    sm[t] = s;
    __syncthreads();
    #pragma unroll
    for (int off = 1; off < SCAN_BS; off <<= 1) {
        int v = (t >= off) ? sm[t - off] : 0;
        __syncthreads();
        sm[t] += v;
        __syncthreads();
    }
    if (i < N_NODES) g_rowstart[i] = sm[t] - s;        // exclusive within block
    if (t == SCAN_BS - 1) g_bsum[blockIdx.x] = sm[t];  // block total
}

__global__ void scanB_kernel() {
    __shared__ int sm[128];
    int t = threadIdx.x;   // 128 threads
    int s = (t < SCAN_NB) ? g_bsum[t] : 0;
    sm[t] = s;
    __syncthreads();
    #pragma unroll
    for (int off = 1; off < 128; off <<= 1) {
        int v = (t >= off) ? sm[t - off] : 0;
        __syncthreads();
        sm[t] += v;
        __syncthreads();
    }
    if (t < SCAN_NB) g_bsumx[t] = sm[t] - s;           // exclusive block offsets
}

__global__ void scanC_kernel() {
    int i = blockIdx.x * blockDim.x + threadIdx.x;
    if (i < N_NODES) {
        int rs = g_rowstart[i] + g_bsumx[i / SCAN_BS];
        g_rowstart[i] = rs;
        g_pos[i] = rs;
    }
    if (i == 0) g_rowstart[N_NODES] = N_EDGES;
}

// ---------------- CSR fill -----------------------------------------------------
__global__ void fill_kernel(const int* __restrict__ src, const int* __restrict__ dst) {
    int e = blockIdx.x * blockDim.x + threadIdx.x;
    if (e >= N_EDGES) return;
    unsigned d = (unsigned)dst[e];
    unsigned s = (unsigned)src[e];
    if (d >= N_NODES || s >= N_NODES) return;
    int slot = atomicAdd(&g_pos[d], 1);
    g_csr[slot] = (int)s;
}

// ---------------- SGEMM device body: 128xBN tile, 8x(BN/16) microtile ----------
template <int BN>
__device__ __forceinline__ void sgemm_body(const float* __restrict__ A,
                                           const float* __restrict__ B,
                                           float* __restrict__ C, int M) {
    constexpr int BM = 128, BK = 16, KD = 128;
    constexpr int TN = BN / 16;                 // 8 (BN=128) or 4 (BN=64)
    __shared__ float As[BK][BM];                // transposed A tile
    __shared__ float Bs[BK][BN];

    const int tid = threadIdx.x;                // 256 threads
    const int tx = tid & 15;
    const int ty = tid >> 4;
    const int row0 = blockIdx.y * BM;

    float acc[8][TN] = {};

    for (int k0 = 0; k0 < KD; k0 += BK) {
        // load A tile (2048 elems, 8 per thread), store transposed
        {
            int idx = tid * 8;
            int m = idx >> 4, kk = idx & 15;    // kk in {0, 8}
            int r = row0 + m;
            float4 f0 = make_float4(0.f, 0.f, 0.f, 0.f), f1 = f0;
            if (r < M) {
                f0 = *(const float4*)&A[(size_t)r * KD + k0 + kk];
                f1 = *(const float4*)&A[(size_t)r * KD + k0 + kk + 4];
            }
            As[kk + 0][m] = f0.x; As[kk + 1][m] = f0.y;
            As[kk + 2][m] = f0.z; As[kk + 3][m] = f0.w;
            As[kk + 4][m] = f1.x; As[kk + 5][m] = f1.y;
            As[kk + 6][m] = f1.z; As[kk + 7][m] = f1.w;
        }
        // load B tile
        if constexpr (BN == 128) {
            int idx = tid * 8;
            int kb = idx >> 7, n = idx & 127;
            const float* bp = &B[(size_t)(k0 + kb) * BN + n];
            *(float4*)&Bs[kb][n]     = *(const float4*)bp;
            *(float4*)&Bs[kb][n + 4] = *(const float4*)(bp + 4);
        } else {
            int idx = tid * 4;
            int kb = idx >> 6, n = idx & 63;
            *(float4*)&Bs[kb][n] = *(const float4*)&B[(size_t)(k0 + kb) * BN + n];
        }
        __syncthreads();

        #pragma unroll
        for (int k = 0; k < BK; k++) {
            float a[8];
            *(float4*)&a[0] = *(const float4*)&As[k][ty * 8];
            *(float4*)&a[4] = *(const float4*)&As[k][ty * 8 + 4];
            float b[TN];
            #pragma unroll
            for (int j = 0; j < TN; j += 4)
                *(float4*)&b[j] = *(const float4*)&Bs[k][tx * TN + j];
            #pragma unroll
            for (int i = 0; i < 8; i++)
                #pragma unroll
                for (int j = 0; j < TN; j++)
                    acc[i][j] += a[i] * b[j];
        }
        __syncthreads();
    }

    #pragma unroll
    for (int i = 0; i < 8; i++) {
        int r = row0 + ty * 8 + i;
        if (r < M) {
            float s = g_dinv[r];     // fold dinv[row] into the product
            #pragma unroll
            for (int j = 0; j < TN; j += 4) {
                float4 v;
                v.x = acc[i][j + 0] * s; v.y = acc[i][j + 1] * s;
                v.z = acc[i][j + 2] * s; v.w = acc[i][j + 3] * s;
                *(float4*)&C[(size_t)r * BN + tx * TN + j] = v;
            }
        }
    }
}

// wrappers: device-side references to the globals (host must NOT touch them)
__global__ void gemm1_kernel(const float* __restrict__ x, const float* __restrict__ W1) {
    sgemm_body<HID_DIM>(x, W1, g_xw, N_NODES);
}
__global__ void gemm2_kernel(const float* __restrict__ W2) {
    sgemm_body<OUT_DIM>(g_h, W2, g_hw, N_NODES);
}

// ---------------- gather layer 1: warp per node, fused self+bias+relu ----------
// h[d] = relu( dinv[d] * ( sum_{s in N(d)} xw'[s] + xw'[d] ) + b1 )
__global__ void gather1_kernel(const float* __restrict__ b1) {
    int w = (blockIdx.x * blockDim.x + threadIdx.x) >> 5;
    int lane = threadIdx.x & 31;
    if (w >= N_NODES) return;
    int beg = g_rowstart[w];
    int end = g_rowstart[w + 1];
    const float4* xw4 = reinterpret_cast<const float4*>(g_xw);

    float4 acc = xw4[(size_t)w * 32 + lane];    // self term xw'[d]
    int e = beg;
    for (; e + 1 < end; e += 2) {
        int s0 = __ldg(&g_csr[e]);
        int s1 = __ldg(&g_csr[e + 1]);
        float4 v0 = xw4[(size_t)s0 * 32 + lane];
        float4 v1 = xw4[(size_t)s1 * 32 + lane];
        acc.x += v0.x + v1.x; acc.y += v0.y + v1.y;
        acc.z += v0.z + v1.z; acc.w += v0.w + v1.w;
    }
    if (e < end) {
        int s0 = __ldg(&g_csr[e]);
        float4 v0 = xw4[(size_t)s0 * 32 + lane];
        acc.x += v0.x; acc.y += v0.y; acc.z += v0.z; acc.w += v0.w;
    }
    float di = g_dinv[w];
    float4 bb = reinterpret_cast<const float4*>(b1)[lane];
    float4 r;
    r.x = fmaxf(di * acc.x + bb.x, 0.f);
    r.y = fmaxf(di * acc.y + bb.y, 0.f);
    r.z = fmaxf(di * acc.z + bb.z, 0.f);
    r.w = fmaxf(di * acc.w + bb.w, 0.f);
    reinterpret_cast<float4*>(g_h)[(size_t)w * 32 + lane] = r;
}

// ---------------- gather layer 2 + FC + leaky, fully fused ---------------------
// v[d] = dinv[d]*(sum hw'[s] + hw'[d]) + b2 ;  out[d] = leaky(v @ Wfc + bfc)
__global__ void gather2_kernel(const float* __restrict__ b2,
                               const float* __restrict__ Wfc,
                               const float* __restrict__ bfc,
                               float* __restrict__ out) {
    int w = (blockIdx.x * blockDim.x + threadIdx.x) >> 5;
    int lane = threadIdx.x & 31;
    if (w >= N_NODES) return;
    int beg = g_rowstart[w];
    int end = g_rowstart[w + 1];
    const float2* hw2 = reinterpret_cast<const float2*>(g_hw);   // 32 float2/row

    float2 acc = hw2[(size_t)w * 32 + lane];    // self term
    int e = beg;
    for (; e + 1 < end; e += 2) {
        int s0 = __ldg(&g_csr[e]);
        int s1 = __ldg(&g_csr[e + 1]);
        float2 v0 = hw2[(size_t)s0 * 32 + lane];
        float2 v1 = hw2[(size_t)s1 * 32 + lane];
        acc.x += v0.x + v1.x; acc.y += v0.y + v1.y;
    }
    if (e < end) {
        int s0 = __ldg(&g_csr[e]);
        float2 v0 = hw2[(size_t)s0 * 32 + lane];
        acc.x += v0.x; acc.y += v0.y;
    }
    float di = g_dinv[w];
    float2 b2v = reinterpret_cast<const float2*>(b2)[lane];
    float vx = di * acc.x + b2v.x;              // feature 2*lane
    float vy = di * acc.y + b2v.y;              // feature 2*lane+1

    // FC: Wfc is [64][2] row-major
    int f0 = 2 * lane, f1 = 2 * lane + 1;
    float p0 = vx * __ldg(&Wfc[f0 * 2 + 0]) + vy * __ldg(&Wfc[f1 * 2 + 0]);
    float p1 = vx * __ldg(&Wfc[f0 * 2 + 1]) + vy * __ldg(&Wfc[f1 * 2 + 1]);
    #pragma unroll
    for (int off = 16; off > 0; off >>= 1) {
        p0 += __shfl_xor_sync(0xffffffff, p0, off);
        p1 += __shfl_xor_sync(0xffffffff, p1, off);
    }
    if (lane == 0) {
        float o0 = p0 + __ldg(&bfc[0]);
        float o1 = p1 + __ldg(&bfc[1]);
        out[w * 2 + 0] = (o0 > 0.f) ? o0 : 0.01f * o0;
        out[w * 2 + 1] = (o1 > 0.f) ? o1 : 0.01f * o1;
    }
}

// ---------------- launch -------------------------------------------------------
extern "C" void kernel_launch(void* const* d_in, const int* in_sizes, int n_in,
                              void* d_out, int out_size) {
    const float* x   = (const float*)d_in[0];
    const int*   ei  = (const int*)d_in[1];   // JAX default: int64 demoted to int32
    const float* W1  = (const float*)d_in[2];
    const float* b1  = (const float*)d_in[3];
    const float* W2  = (const float*)d_in[4];
    const float* b2  = (const float*)d_in[5];
    const float* Wfc = (const float*)d_in[6];
    const float* bfc = (const float*)d_in[7];
    float* out = (float*)d_out;

    const int* src = ei;
    const int* dst = ei + N_EDGES;

    // degree + dinv + CSR
    zero_deg_kernel<<<(N_NODES + 255) / 256, 256>>>();
    deg_kernel<<<(N_EDGES + 255) / 256, 256>>>(dst);
    dinv_kernel<<<(N_NODES + 255) / 256, 256>>>();
    scanA_kernel<<<SCAN_NB, SCAN_BS>>>();
    scanB_kernel<<<1, 128>>>();
    scanC_kernel<<<(N_NODES + 255) / 256, 256>>>();
    fill_kernel<<<(N_EDGES + 255) / 256, 256>>>(src, dst);

    // layer 1: xw' = (x@W1)*dinv ; h = relu(dinv*(gather + self) + b1)
    gemm1_kernel<<<dim3(1, (N_NODES + 127) / 128), 256>>>(x, W1);
    gather1_kernel<<<(N_NODES * 32 + 255) / 256, 256>>>(b1);

    // layer 2 fused with FC + leaky relu
    gemm2_kernel<<<dim3(1, (N_NODES + 127) / 128), 256>>>(W2);
    gather2_kernel<<<(N_NODES * 32 + 255) / 256, 256>>>(b2, Wfc, bfc, out);
}

// round 7
// speedup vs baseline: 1.7776x; 1.0737x over previous
#include <cuda_runtime.h>
#include <cuda_bf16.h>
#include <cstdint>

#define N_NODES 50000
#define N_EDGES 800000
#define IN_DIM  128
#define HID_DIM 128
#define OUT_DIM 64

#define SCAN_BS   512
#define SCAN_NB   ((N_NODES + SCAN_BS - 1) / SCAN_BS)   // 98

// ---------------- scratch (device globals: no allocation allowed) -------------
// Only referenced from DEVICE code (host-side use of __device__ symbols gives
// the host shadow address -> silent ATS writes to host RAM; R5 bug).
__device__ __align__(16) int   g_degi    [N_NODES];
__device__ __align__(16) float g_dinv    [N_NODES];
__device__ __align__(16) int   g_rowstart[N_NODES + 1];
__device__ __align__(16) int   g_pos     [N_NODES];
__device__ __align__(16) int   g_csr     [N_EDGES];        // src node per CSR slot
__device__ __align__(16) int   g_bsum    [SCAN_NB];
__device__ __align__(16) int   g_bsumx   [SCAN_NB];
__device__ __align__(16) float g_xw      [N_NODES * HID_DIM];  // (x@W1)*dinv[row]
__device__ __align__(16) float g_h       [N_NODES * HID_DIM];  // layer-1 output
__device__ __align__(16) float g_hw      [N_NODES * OUT_DIM];  // (h@W2)*dinv[row]

// ---------------- packed f32x2 helpers -----------------------------------------
__device__ __forceinline__ unsigned long long pack2(float lo, float hi) {
    unsigned long long r;
    asm("mov.b64 %0, {%1, %2};" : "=l"(r)
        : "r"(__float_as_uint(lo)), "r"(__float_as_uint(hi)));
    return r;
}
__device__ __forceinline__ void unpack2(unsigned long long v, float& lo, float& hi) {
    unsigned a, b;
    asm("mov.b64 {%0, %1}, %2;" : "=r"(a), "=r"(b) : "l"(v));
    lo = __uint_as_float(a); hi = __uint_as_float(b);
}
__device__ __forceinline__ void ffma2(unsigned long long& d,
                                      unsigned long long a, unsigned long long b) {
    asm("fma.rn.f32x2 %0, %1, %2, %0;" : "+l"(d) : "l"(a), "l"(b));
}

// ---------------- degree -------------------------------------------------------
__global__ void zero_deg_kernel() {
    int i = blockIdx.x * blockDim.x + threadIdx.x;
    if (i < N_NODES) g_degi[i] = 0;
}

__global__ void deg_kernel(const int* __restrict__ dst) {
    int e = blockIdx.x * blockDim.x + threadIdx.x;
    if (e >= N_EDGES) return;
    unsigned d = (unsigned)dst[e];
    if (d < N_NODES) atomicAdd(&g_degi[d], 1);
}

// ---------------- exclusive scan of degrees (+ fused dinv) ---------------------
__global__ void scanA_kernel() {
    __shared__ int sm[SCAN_BS];
    int t = threadIdx.x;
    int i = blockIdx.x * SCAN_BS + t;
    int s = (i < N_NODES) ? g_degi[i] : 0;
    if (i < N_NODES) g_dinv[i] = rsqrtf((float)s + 1.0f);   // fused dinv
    sm[t] = s;
    __syncthreads();
    #pragma unroll
    for (int off = 1; off < SCAN_BS; off <<= 1) {
        int v = (t >= off) ? sm[t - off] : 0;
        __syncthreads();
        sm[t] += v;
        __syncthreads();
    }
    if (i < N_NODES) g_rowstart[i] = sm[t] - s;        // exclusive within block
    if (t == SCAN_BS - 1) g_bsum[blockIdx.x] = sm[t];  // block total
}

__global__ void scanB_kernel() {
    __shared__ int sm[128];
    int t = threadIdx.x;   // 128 threads
    int s = (t < SCAN_NB) ? g_bsum[t] : 0;
    sm[t] = s;
    __syncthreads();
    #pragma unroll
    for (int off = 1; off < 128; off <<= 1) {
        int v = (t >= off) ? sm[t - off] : 0;
        __syncthreads();
        sm[t] += v;
        __syncthreads();
    }
    if (t < SCAN_NB) g_bsumx[t] = sm[t] - s;           // exclusive block offsets
}

__global__ void scanC_kernel() {
    int i = blockIdx.x * blockDim.x + threadIdx.x;
    if (i < N_NODES) {
        int rs = g_rowstart[i] + g_bsumx[i / SCAN_BS];
        g_rowstart[i] = rs;
        g_pos[i] = rs;
    }
    if (i == 0) g_rowstart[N_NODES] = N_EDGES;
}

// ---------------- CSR fill -----------------------------------------------------
__global__ void fill_kernel(const int* __restrict__ src, const int* __restrict__ dst) {
    int e = blockIdx.x * blockDim.x + threadIdx.x;
    if (e >= N_EDGES) return;
    unsigned d = (unsigned)dst[e];
    unsigned s = (unsigned)src[e];
    if (d >= N_NODES || s >= N_NODES) return;
    int slot = atomicAdd(&g_pos[d], 1);
    g_csr[slot] = (int)s;
}

// ---------------- SGEMM: 128xBN tile, FFMA2 microkernel ------------------------
// Thread owns 8 rows (ty*8..+7, paired for f32x2) and TN cols.
// Col ownership (conflict-free LDS.128): BN=128 -> {tx*4..+3} u {64+tx*4..+3};
//                                        BN=64  -> {tx*4..+3}.
template <int BN>
__device__ __forceinline__ void sgemm_body(const float* __restrict__ A,
                                           const float* __restrict__ B,
                                           float* __restrict__ C, int M) {
    constexpr int BM = 128, BK = 16, KD = 128;
    constexpr int TN = (BN == 128) ? 8 : 4;
    __shared__ float As[BK][BM];                // transposed A tile
    __shared__ float Bs[BK][BN];

    const int tid = threadIdx.x;                // 256 threads
    const int tx = tid & 15;
    const int ty = tid >> 4;
    const int row0 = blockIdx.y * BM;

    unsigned long long acc2[4][TN] = {};        // [row-pair][col]

    for (int k0 = 0; k0 < KD; k0 += BK) {
        // load A tile (2048 elems, 8 per thread), store transposed
        {
            int idx = tid * 8;
            int m = idx >> 4, kk = idx & 15;    // kk in {0, 8}
            int r = row0 + m;
            float4 f0 = make_float4(0.f, 0.f, 0.f, 0.f), f1 = f0;
            if (r < M) {
                f0 = *(const float4*)&A[(size_t)r * KD + k0 + kk];
                f1 = *(const float4*)&A[(size_t)r * KD + k0 + kk + 4];
            }
            As[kk + 0][m] = f0.x; As[kk + 1][m] = f0.y;
            As[kk + 2][m] = f0.z; As[kk + 3][m] = f0.w;
            As[kk + 4][m] = f1.x; As[kk + 5][m] = f1.y;
            As[kk + 6][m] = f1.z; As[kk + 7][m] = f1.w;
        }
        // load B tile
        if constexpr (BN == 128) {
            int idx = tid * 8;
            int kb = idx >> 7, n = idx & 127;
            const float* bp = &B[(size_t)(k0 + kb) * BN + n];
            *(float4*)&Bs[kb][n]     = *(const float4*)bp;
            *(float4*)&Bs[kb][n + 4] = *(const float4*)(bp + 4);
        } else {
            int idx = tid * 4;
            int kb = idx >> 6, n = idx & 63;
            *(float4*)&Bs[kb][n] = *(const float4*)&B[(size_t)(k0 + kb) * BN + n];
        }
        __syncthreads();

        #pragma unroll
        for (int k = 0; k < BK; k++) {
            float a[8];
            *(float4*)&a[0] = *(const float4*)&As[k][ty * 8];
            *(float4*)&a[4] = *(const float4*)&As[k][ty * 8 + 4];
            float b[TN];
            *(float4*)&b[0] = *(const float4*)&Bs[k][tx * 4];
            if constexpr (BN == 128)
                *(float4*)&b[4] = *(const float4*)&Bs[k][64 + tx * 4];

            unsigned long long a2[4];
            #pragma unroll
            for (int p = 0; p < 4; p++) a2[p] = pack2(a[2 * p], a[2 * p + 1]);
            unsigned long long b2[TN];
            #pragma unroll
            for (int j = 0; j < TN; j++) b2[j] = pack2(b[j], b[j]);

            #pragma unroll
            for (int p = 0; p < 4; p++)
                #pragma unroll
                for (int j = 0; j < TN; j++)
                    ffma2(acc2[p][j], a2[p], b2[j]);
        }
        __syncthreads();
    }

    #pragma unroll
    for (int p = 0; p < 4; p++) {
        int r0 = row0 + ty * 8 + 2 * p;
        if (r0 >= M) continue;
        float s0 = g_dinv[r0];
        float s1 = (r0 + 1 < M) ? g_dinv[r0 + 1] : 0.f;
        float v0[TN], v1[TN];
        #pragma unroll
        for (int j = 0; j < TN; j++) {
            float lo, hi;
            unpack2(acc2[p][j], lo, hi);
            v0[j] = lo * s0; v1[j] = hi * s1;
        }
        *(float4*)&C[(size_t)r0 * BN + tx * 4] = *(float4*)&v0[0];
        if (r0 + 1 < M)
            *(float4*)&C[(size_t)(r0 + 1) * BN + tx * 4] = *(float4*)&v1[0];
        if constexpr (BN == 128) {
            *(float4*)&C[(size_t)r0 * BN + 64 + tx * 4] = *(float4*)&v0[4];
            if (r0 + 1 < M)
                *(float4*)&C[(size_t)(r0 + 1) * BN + 64 + tx * 4] = *(float4*)&v1[4];
        }
    }
}

// wrappers: device-side references to the globals (host must NOT touch them)
__global__ void gemm1_kernel(const float* __restrict__ x, const float* __restrict__ W1) {
    sgemm_body<HID_DIM>(x, W1, g_xw, N_NODES);
}
__global__ void gemm2_kernel(const float* __restrict__ W2) {
    sgemm_body<OUT_DIM>(g_h, W2, g_hw, N_NODES);
}

// ---------------- gather layer 1: warp per node, fused self+bias+relu ----------
// h[d] = relu( dinv[d] * ( sum_{s in N(d)} xw'[s] + xw'[d] ) + b1 )
__global__ void gather1_kernel(const float* __restrict__ b1) {
    int w = (blockIdx.x * blockDim.x + threadIdx.x) >> 5;
    int lane = threadIdx.x & 31;
    if (w >= N_NODES) return;
    int beg = g_rowstart[w];
    int end = g_rowstart[w + 1];
    const float4* xw4 = reinterpret_cast<const float4*>(g_xw);

    float4 acc = xw4[(size_t)w * 32 + lane];    // self term xw'[d]
    int e = beg;
    for (; e + 3 < end; e += 4) {
        int s0 = __ldg(&g_csr[e]);
        int s1 = __ldg(&g_csr[e + 1]);
        int s2 = __ldg(&g_csr[e + 2]);
        int s3 = __ldg(&g_csr[e + 3]);
        float4 v0 = xw4[(size_t)s0 * 32 + lane];
        float4 v1 = xw4[(size_t)s1 * 32 + lane];
        float4 v2 = xw4[(size_t)s2 * 32 + lane];
        float4 v3 = xw4[(size_t)s3 * 32 + lane];
        acc.x += (v0.x + v1.x) + (v2.x + v3.x);
        acc.y += (v0.y + v1.y) + (v2.y + v3.y);
        acc.z += (v0.z + v1.z) + (v2.z + v3.z);
        acc.w += (v0.w + v1.w) + (v2.w + v3.w);
    }
    for (; e < end; e++) {
        int s0 = __ldg(&g_csr[e]);
        float4 v0 = xw4[(size_t)s0 * 32 + lane];
        acc.x += v0.x; acc.y += v0.y; acc.z += v0.z; acc.w += v0.w;
    }
    float di = g_dinv[w];
    float4 bb = reinterpret_cast<const float4*>(b1)[lane];
    float4 r;
    r.x = fmaxf(di * acc.x + bb.x, 0.f);
    r.y = fmaxf(di * acc.y + bb.y, 0.f);
    r.z = fmaxf(di * acc.z + bb.z, 0.f);
    r.w = fmaxf(di * acc.w + bb.w, 0.f);
    reinterpret_cast<float4*>(g_h)[(size_t)w * 32 + lane] = r;
}

// ---------------- gather layer 2 + FC + leaky, fully fused ---------------------
// v[d] = dinv[d]*(sum hw'[s] + hw'[d]) + b2 ;  out[d] = leaky(v @ Wfc + bfc)
__global__ void gather2_kernel(const float* __restrict__ b2,
                               const float* __restrict__ Wfc,
                               const float* __restrict__ bfc,
                               float* __restrict__ out) {
    int w = (blockIdx.x * blockDim.x + threadIdx.x) >> 5;
    int lane = threadIdx.x & 31;
    if (w >= N_NODES) return;
    int beg = g_rowstart[w];
    int end = g_rowstart[w + 1];
    const float2* hw2 = reinterpret_cast<const float2*>(g_hw);   // 32 float2/row

    float2 acc = hw2[(size_t)w * 32 + lane];    // self term
    int e = beg;
    for (; e + 3 < end; e += 4) {
        int s0 = __ldg(&g_csr[e]);
        int s1 = __ldg(&g_csr[e + 1]);
        int s2 = __ldg(&g_csr[e + 2]);
        int s3 = __ldg(&g_csr[e + 3]);
        float2 v0 = hw2[(size_t)s0 * 32 + lane];
        float2 v1 = hw2[(size_t)s1 * 32 + lane];
        float2 v2 = hw2[(size_t)s2 * 32 + lane];
        float2 v3 = hw2[(size_t)s3 * 32 + lane];
        acc.x += (v0.x + v1.x) + (v2.x + v3.x);
        acc.y += (v0.y + v1.y) + (v2.y + v3.y);
    }
    for (; e < end; e++) {
        int s0 = __ldg(&g_csr[e]);
        float2 v0 = hw2[(size_t)s0 * 32 + lane];
        acc.x += v0.x; acc.y += v0.y;
    }
    float di = g_dinv[w];
    float2 b2v = reinterpret_cast<const float2*>(b2)[lane];
    float vx = di * acc.x + b2v.x;              // feature 2*lane
    float vy = di * acc.y + b2v.y;              // feature 2*lane+1

    // FC: Wfc is [64][2] row-major
    int f0 = 2 * lane, f1 = 2 * lane + 1;
    float p0 = vx * __ldg(&Wfc[f0 * 2 + 0]) + vy * __ldg(&Wfc[f1 * 2 + 0]);
    float p1 = vx * __ldg(&Wfc[f0 * 2 + 1]) + vy * __ldg(&Wfc[f1 * 2 + 1]);
    #pragma unroll
    for (int off = 16; off > 0; off >>= 1) {
        p0 += __shfl_xor_sync(0xffffffff, p0, off);
        p1 += __shfl_xor_sync(0xffffffff, p1, off);
    }
    if (lane == 0) {
        float o0 = p0 + __ldg(&bfc[0]);
        float o1 = p1 + __ldg(&bfc[1]);
        out[w * 2 + 0] = (o0 > 0.f) ? o0 : 0.01f * o0;
        out[w * 2 + 1] = (o1 > 0.f) ? o1 : 0.01f * o1;
    }
}

// ---------------- launch -------------------------------------------------------
extern "C" void kernel_launch(void* const* d_in, const int* in_sizes, int n_in,
                              void* d_out, int out_size) {
    const float* x   = (const float*)d_in[0];
    const int*   ei  = (const int*)d_in[1];   // JAX default: int64 demoted to int32
    const float* W1  = (const float*)d_in[2];
    const float* b1  = (const float*)d_in[3];
    const float* W2  = (const float*)d_in[4];
    const float* b2  = (const float*)d_in[5];
    const float* Wfc = (const float*)d_in[6];
    const float* bfc = (const float*)d_in[7];
    float* out = (float*)d_out;

    const int* src = ei;
    const int* dst = ei + N_EDGES;

    // degree + dinv + CSR
    zero_deg_kernel<<<(N_NODES + 255) / 256, 256>>>();
    deg_kernel<<<(N_EDGES + 255) / 256, 256>>>(dst);
    scanA_kernel<<<SCAN_NB, SCAN_BS>>>();       // also computes dinv
    scanB_kernel<<<1, 128>>>();
    scanC_kernel<<<(N_NODES + 255) / 256, 256>>>();
    fill_kernel<<<(N_EDGES + 255) / 256, 256>>>(src, dst);

    // layer 1: xw' = (x@W1)*dinv ; h = relu(dinv*(gather + self) + b1)
    gemm1_kernel<<<dim3(1, (N_NODES + 127) / 128), 256>>>(x, W1);
    gather1_kernel<<<(N_NODES * 32 + 255) / 256, 256>>>(b1);

    // layer 2 fused with FC + leaky relu
    gemm2_kernel<<<dim3(1, (N_NODES + 127) / 128), 256>>>(W2);
    gather2_kernel<<<(N_NODES * 32 + 255) / 256, 256>>>(b2, Wfc, bfc, out);
}

// round 8
// speedup vs baseline: 1.8876x; 1.0619x over previous
#include <cuda_runtime.h>
#include <cuda_bf16.h>
#include <cstdint>

#define N_NODES 50000
#define N_EDGES 800000
#define IN_DIM  128
#define HID_DIM 128
#define OUT_DIM 64

#define SCAN_BS   512
#define SCAN_NB   ((N_NODES + SCAN_BS - 1) / SCAN_BS)   // 98

// ---------------- scratch (device globals: no allocation allowed) -------------
// Only referenced from DEVICE code (host-side use of __device__ symbols gives
// the host shadow address -> silent ATS writes to host RAM; R5 bug).
__device__ __align__(16) int   g_degi    [N_NODES];
__device__ __align__(16) float g_dinv    [N_NODES];
__device__ __align__(16) int   g_rowstart[N_NODES + 1];
__device__ __align__(16) int   g_pos     [N_NODES];
__device__ __align__(16) int   g_csr     [N_EDGES];        // src node per CSR slot
__device__ __align__(16) int   g_bsum    [SCAN_NB];
__device__ __align__(16) int   g_bsumx   [SCAN_NB];
__device__ __align__(16) float g_xw      [N_NODES * HID_DIM];  // x @ W1 (UNscaled)
__device__ __align__(16) float g_h       [N_NODES * HID_DIM];  // layer-1 output
__device__ __align__(16) float g_hw      [N_NODES * OUT_DIM];  // (h@W2)*dinv[row]

// ---------------- packed f32x2 helpers -----------------------------------------
__device__ __forceinline__ unsigned long long pack2(float lo, float hi) {
    unsigned long long r;
    asm("mov.b64 %0, {%1, %2};" : "=l"(r)
        : "r"(__float_as_uint(lo)), "r"(__float_as_uint(hi)));
    return r;
}
__device__ __forceinline__ void unpack2(unsigned long long v, float& lo, float& hi) {
    unsigned a, b;
    asm("mov.b64 {%0, %1}, %2;" : "=r"(a), "=r"(b) : "l"(v));
    lo = __uint_as_float(a); hi = __uint_as_float(b);
}
__device__ __forceinline__ void ffma2(unsigned long long& d,
                                      unsigned long long a, unsigned long long b) {
    asm("fma.rn.f32x2 %0, %1, %2, %0;" : "+l"(d) : "l"(a), "l"(b));
}

// ---------------- degree -------------------------------------------------------
__global__ void zero_deg_kernel() {
    int i = blockIdx.x * blockDim.x + threadIdx.x;
    if (i < N_NODES) g_degi[i] = 0;
}

__global__ void deg_kernel(const int* __restrict__ dst) {
    int e = blockIdx.x * blockDim.x + threadIdx.x;
    if (e >= N_EDGES) return;
    unsigned d = (unsigned)dst[e];
    if (d < N_NODES) atomicAdd(&g_degi[d], 1);
}

// ---------------- exclusive scan of degrees (+ fused dinv) ---------------------
__global__ void scanA_kernel() {
    __shared__ int sm[SCAN_BS];
    int t = threadIdx.x;
    int i = blockIdx.x * SCAN_BS + t;
    int s = (i < N_NODES) ? g_degi[i] : 0;
    if (i < N_NODES) g_dinv[i] = rsqrtf((float)s + 1.0f);   // fused dinv
    sm[t] = s;
    __syncthreads();
    #pragma unroll
    for (int off = 1; off < SCAN_BS; off <<= 1) {
        int v = (t >= off) ? sm[t - off] : 0;
        __syncthreads();
        sm[t] += v;
        __syncthreads();
    }
    if (i < N_NODES) g_rowstart[i] = sm[t] - s;        // exclusive within block
    if (t == SCAN_BS - 1) g_bsum[blockIdx.x] = sm[t];  // block total
}

__global__ void scanB_kernel() {
    __shared__ int sm[128];
    int t = threadIdx.x;   // 128 threads
    int s = (t < SCAN_NB) ? g_bsum[t] : 0;
    sm[t] = s;
    __syncthreads();
    #pragma unroll
    for (int off = 1; off < 128; off <<= 1) {
        int v = (t >= off) ? sm[t - off] : 0;
        __syncthreads();
        sm[t] += v;
        __syncthreads();
    }
    if (t < SCAN_NB) g_bsumx[t] = sm[t] - s;           // exclusive block offsets
}

__global__ void scanC_kernel() {
    int i = blockIdx.x * blockDim.x + threadIdx.x;
    if (i < N_NODES) {
        int rs = g_rowstart[i] + g_bsumx[i / SCAN_BS];
        g_rowstart[i] = rs;
        g_pos[i] = rs;
    }
    if (i == 0) g_rowstart[N_NODES] = N_EDGES;
}

// ---------------- CSR fill -----------------------------------------------------
__global__ void fill_kernel(const int* __restrict__ src, const int* __restrict__ dst) {
    int e = blockIdx.x * blockDim.x + threadIdx.x;
    if (e >= N_EDGES) return;
    unsigned d = (unsigned)dst[e];
    unsigned s = (unsigned)src[e];
    if (d >= N_NODES || s >= N_NODES) return;
    int slot = atomicAdd(&g_pos[d], 1);
    g_csr[slot] = (int)s;
}

// ---------------- SGEMM: 128xBN tile, FFMA2 microkernel ------------------------
// SCALE_DINV: fold g_dinv[row] into the epilogue (layer 2 only; layer 1 runs
// concurrently with the degree chain, so dinv is applied per-edge in gather1).
template <int BN, bool SCALE_DINV>
__device__ __forceinline__ void sgemm_body(const float* __restrict__ A,
                                           const float* __restrict__ B,
                                           float* __restrict__ C, int M) {
    constexpr int BM = 128, BK = 16, KD = 128;
    constexpr int TN = (BN == 128) ? 8 : 4;
    __shared__ float As[BK][BM];                // transposed A tile
    __shared__ float Bs[BK][BN];

    const int tid = threadIdx.x;                // 256 threads
    const int tx = tid & 15;
    const int ty = tid >> 4;
    const int row0 = blockIdx.y * BM;

    unsigned long long acc2[4][TN] = {};        // [row-pair][col]

    for (int k0 = 0; k0 < KD; k0 += BK) {
        // load A tile (2048 elems, 8 per thread), store transposed
        {
            int idx = tid * 8;
            int m = idx >> 4, kk = idx & 15;    // kk in {0, 8}
            int r = row0 + m;
            float4 f0 = make_float4(0.f, 0.f, 0.f, 0.f), f1 = f0;
            if (r < M) {
                f0 = *(const float4*)&A[(size_t)r * KD + k0 + kk];
                f1 = *(const float4*)&A[(size_t)r * KD + k0 + kk + 4];
            }
            As[kk + 0][m] = f0.x; As[kk + 1][m] = f0.y;
            As[kk + 2][m] = f0.z; As[kk + 3][m] = f0.w;
            As[kk + 4][m] = f1.x; As[kk + 5][m] = f1.y;
            As[kk + 6][m] = f1.z; As[kk + 7][m] = f1.w;
        }
        // load B tile
        if constexpr (BN == 128) {
            int idx = tid * 8;
            int kb = idx >> 7, n = idx & 127;
            const float* bp = &B[(size_t)(k0 + kb) * BN + n];
            *(float4*)&Bs[kb][n]     = *(const float4*)bp;
            *(float4*)&Bs[kb][n + 4] = *(const float4*)(bp + 4);
        } else {
            int idx = tid * 4;
            int kb = idx >> 6, n = idx & 63;
            *(float4*)&Bs[kb][n] = *(const float4*)&B[(size_t)(k0 + kb) * BN + n];
        }
        __syncthreads();

        #pragma unroll
        for (int k = 0; k < BK; k++) {
            float a[8];
            *(float4*)&a[0] = *(const float4*)&As[k][ty * 8];
            *(float4*)&a[4] = *(const float4*)&As[k][ty * 8 + 4];
            float b[TN];
            *(float4*)&b[0] = *(const float4*)&Bs[k][tx * 4];
            if constexpr (BN == 128)
                *(float4*)&b[4] = *(const float4*)&Bs[k][64 + tx * 4];

            unsigned long long a2[4];
            #pragma unroll
            for (int p = 0; p < 4; p++) a2[p] = pack2(a[2 * p], a[2 * p + 1]);
            unsigned long long b2[TN];
            #pragma unroll
            for (int j = 0; j < TN; j++) b2[j] = pack2(b[j], b[j]);

            #pragma unroll
            for (int p = 0; p < 4; p++)
                #pragma unroll
                for (int j = 0; j < TN; j++)
                    ffma2(acc2[p][j], a2[p], b2[j]);
        }
        __syncthreads();
    }

    #pragma unroll
    for (int p = 0; p < 4; p++) {
        int r0 = row0 + ty * 8 + 2 * p;
        if (r0 >= M) continue;
        float s0 = 1.f, s1 = 1.f;
        if constexpr (SCALE_DINV) {
            s0 = g_dinv[r0];
            s1 = (r0 + 1 < M) ? g_dinv[r0 + 1] : 0.f;
        }
        float v0[TN], v1[TN];
        #pragma unroll
        for (int j = 0; j < TN; j++) {
            float lo, hi;
            unpack2(acc2[p][j], lo, hi);
            v0[j] = lo * s0; v1[j] = hi * s1;
        }
        *(float4*)&C[(size_t)r0 * BN + tx * 4] = *(float4*)&v0[0];
        if (r0 + 1 < M)
            *(float4*)&C[(size_t)(r0 + 1) * BN + tx * 4] = *(float4*)&v1[0];
        if constexpr (BN == 128) {
            *(float4*)&C[(size_t)r0 * BN + 64 + tx * 4] = *(float4*)&v0[4];
            if (r0 + 1 < M)
                *(float4*)&C[(size_t)(r0 + 1) * BN + 64 + tx * 4] = *(float4*)&v1[4];
        }
    }
}

// wrappers: device-side references to the globals (host must NOT touch them)
__global__ void gemm1_kernel(const float* __restrict__ x, const float* __restrict__ W1) {
    sgemm_body<HID_DIM, false>(x, W1, g_xw, N_NODES);   // unscaled: no dinv dep
}
__global__ void gemm2_kernel(const float* __restrict__ W2) {
    sgemm_body<OUT_DIM, true>(g_h, W2, g_hw, N_NODES);
}

// ---------------- gather layer 1: warp per node, per-edge dinv[s] --------------
// h[d] = relu( dinv[d] * ( sum_s xw[s]*dinv[s] + xw[d]*dinv[d] ) + b1 )
__global__ void gather1_kernel(const float* __restrict__ b1) {
    int w = (blockIdx.x * blockDim.x + threadIdx.x) >> 5;
    int lane = threadIdx.x & 31;
    if (w >= N_NODES) return;
    int beg = g_rowstart[w];
    int end = g_rowstart[w + 1];
    const float4* xw4 = reinterpret_cast<const float4*>(g_xw);

    float dself = g_dinv[w];
    float4 self = xw4[(size_t)w * 32 + lane];
    float4 acc;
    acc.x = self.x * dself; acc.y = self.y * dself;
    acc.z = self.z * dself; acc.w = self.w * dself;

    int e = beg;
    for (; e + 3 < end; e += 4) {
        int s0 = __ldg(&g_csr[e]);
        int s1 = __ldg(&g_csr[e + 1]);
        int s2 = __ldg(&g_csr[e + 2]);
        int s3 = __ldg(&g_csr[e + 3]);
        float d0 = __ldg(&g_dinv[s0]);
        float d1 = __ldg(&g_dinv[s1]);
        float d2 = __ldg(&g_dinv[s2]);
        float d3 = __ldg(&g_dinv[s3]);
        float4 v0 = xw4[(size_t)s0 * 32 + lane];
        float4 v1 = xw4[(size_t)s1 * 32 + lane];
        float4 v2 = xw4[(size_t)s2 * 32 + lane];
        float4 v3 = xw4[(size_t)s3 * 32 + lane];
        acc.x = fmaf(v0.x, d0, fmaf(v1.x, d1, fmaf(v2.x, d2, fmaf(v3.x, d3, acc.x))));
        acc.y = fmaf(v0.y, d0, fmaf(v1.y, d1, fmaf(v2.y, d2, fmaf(v3.y, d3, acc.y))));
        acc.z = fmaf(v0.z, d0, fmaf(v1.z, d1, fmaf(v2.z, d2, fmaf(v3.z, d3, acc.z))));
        acc.w = fmaf(v0.w, d0, fmaf(v1.w, d1, fmaf(v2.w, d2, fmaf(v3.w, d3, acc.w))));
    }
    for (; e < end; e++) {
        int s0 = __ldg(&g_csr[e]);
        float d0 = __ldg(&g_dinv[s0]);
        float4 v0 = xw4[(size_t)s0 * 32 + lane];
        acc.x = fmaf(v0.x, d0, acc.x); acc.y = fmaf(v0.y, d0, acc.y);
        acc.z = fmaf(v0.z, d0, acc.z); acc.w = fmaf(v0.w, d0, acc.w);
    }
    float4 bb = reinterpret_cast<const float4*>(b1)[lane];
    float4 r;
    r.x = fmaxf(fmaf(dself, acc.x, bb.x), 0.f);
    r.y = fmaxf(fmaf(dself, acc.y, bb.y), 0.f);
    r.z = fmaxf(fmaf(dself, acc.z, bb.z), 0.f);
    r.w = fmaxf(fmaf(dself, acc.w, bb.w), 0.f);
    reinterpret_cast<float4*>(g_h)[(size_t)w * 32 + lane] = r;
}

// ---------------- gather layer 2 + FC + leaky, fully fused ---------------------
// v[d] = dinv[d]*(sum hw'[s] + hw'[d]) + b2 ;  out[d] = leaky(v @ Wfc + bfc)
__global__ void gather2_kernel(const float* __restrict__ b2,
                               const float* __restrict__ Wfc,
                               const float* __restrict__ bfc,
                               float* __restrict__ out) {
    int w = (blockIdx.x * blockDim.x + threadIdx.x) >> 5;
    int lane = threadIdx.x & 31;
    if (w >= N_NODES) return;
    int beg = g_rowstart[w];
    int end = g_rowstart[w + 1];
    const float2* hw2 = reinterpret_cast<const float2*>(g_hw);   // 32 float2/row

    float2 acc = hw2[(size_t)w * 32 + lane];    // self term (hw' already scaled)
    int e = beg;
    for (; e + 3 < end; e += 4) {
        int s0 = __ldg(&g_csr[e]);
        int s1 = __ldg(&g_csr[e + 1]);
        int s2 = __ldg(&g_csr[e + 2]);
        int s3 = __ldg(&g_csr[e + 3]);
        float2 v0 = hw2[(size_t)s0 * 32 + lane];
        float2 v1 = hw2[(size_t)s1 * 32 + lane];
        float2 v2 = hw2[(size_t)s2 * 32 + lane];
        float2 v3 = hw2[(size_t)s3 * 32 + lane];
        acc.x += (v0.x + v1.x) + (v2.x + v3.x);
        acc.y += (v0.y + v1.y) + (v2.y + v3.y);
    }
    for (; e < end; e++) {
        int s0 = __ldg(&g_csr[e]);
        float2 v0 = hw2[(size_t)s0 * 32 + lane];
        acc.x += v0.x; acc.y += v0.y;
    }
    float di = g_dinv[w];
    float2 b2v = reinterpret_cast<const float2*>(b2)[lane];
    float vx = di * acc.x + b2v.x;              // feature 2*lane
    float vy = di * acc.y + b2v.y;              // feature 2*lane+1

    // FC: Wfc is [64][2] row-major
    int f0 = 2 * lane, f1 = 2 * lane + 1;
    float p0 = vx * __ldg(&Wfc[f0 * 2 + 0]) + vy * __ldg(&Wfc[f1 * 2 + 0]);
    float p1 = vx * __ldg(&Wfc[f0 * 2 + 1]) + vy * __ldg(&Wfc[f1 * 2 + 1]);
    #pragma unroll
    for (int off = 16; off > 0; off >>= 1) {
        p0 += __shfl_xor_sync(0xffffffff, p0, off);
        p1 += __shfl_xor_sync(0xffffffff, p1, off);
    }
    if (lane == 0) {
        float o0 = p0 + __ldg(&bfc[0]);
        float o1 = p1 + __ldg(&bfc[1]);
        out[w * 2 + 0] = (o0 > 0.f) ? o0 : 0.01f * o0;
        out[w * 2 + 1] = (o1 > 0.f) ? o1 : 0.01f * o1;
    }
}

// ---------------- launch -------------------------------------------------------
// Fork-join: gemm1 (stream 0) runs concurrently with the degree/CSR chain
// (side stream). Streams/events are created once (host-side objects only; no
// device allocation). The same graph is produced on every call.
extern "C" void kernel_launch(void* const* d_in, const int* in_sizes, int n_in,
                              void* d_out, int out_size) {
    const float* x   = (const float*)d_in[0];
    const int*   ei  = (const int*)d_in[1];   // JAX default: int64 demoted to int32
    const float* W1  = (const float*)d_in[2];
    const float* b1  = (const float*)d_in[3];
    const float* W2  = (const float*)d_in[4];
    const float* b2  = (const float*)d_in[5];
    const float* Wfc = (const float*)d_in[6];
    const float* bfc = (const float*)d_in[7];
    float* out = (float*)d_out;

    const int* src = ei;
    const int* dst = ei + N_EDGES;

    static cudaStream_t s_side = nullptr;
    static cudaEvent_t  e_fork = nullptr, e_join = nullptr;
    if (s_side == nullptr) {
        cudaStreamCreateWithFlags(&s_side, cudaStreamNonBlocking);
        cudaEventCreateWithFlags(&e_fork, cudaEventDisableTiming);
        cudaEventCreateWithFlags(&e_join, cudaEventDisableTiming);
    }

    // fork side stream off the (captured) default stream
    cudaEventRecord(e_fork, 0);
    cudaStreamWaitEvent(s_side, e_fork, 0);

    // side stream: degree + dinv + CSR build
    zero_deg_kernel<<<(N_NODES + 255) / 256, 256, 0, s_side>>>();
    deg_kernel<<<(N_EDGES + 255) / 256, 256, 0, s_side>>>(dst);
    scanA_kernel<<<SCAN_NB, SCAN_BS, 0, s_side>>>();       // also computes dinv
    scanB_kernel<<<1, 128, 0, s_side>>>();
    scanC_kernel<<<(N_NODES + 255) / 256, 256, 0, s_side>>>();
    fill_kernel<<<(N_EDGES + 255) / 256, 256, 0, s_side>>>(src, dst);
    cudaEventRecord(e_join, s_side);

    // default stream: gemm1 (independent of degree chain), then join
    gemm1_kernel<<<dim3(1, (N_NODES + 127) / 128), 256>>>(x, W1);
    cudaStreamWaitEvent(0, e_join, 0);

    // layer 1 aggregation (needs CSR + dinv + xw)
    gather1_kernel<<<(N_NODES * 32 + 255) / 256, 256>>>(b1);

    // layer 2 fused with FC + leaky relu
    gemm2_kernel<<<dim3(1, (N_NODES + 127) / 128), 256>>>(W2);
    gather2_kernel<<<(N_NODES * 32 + 255) / 256, 256>>>(b2, Wfc, bfc, out);
}

// round 9
// speedup vs baseline: 1.9023x; 1.0078x over previous
#include <cuda_runtime.h>
#include <cuda_bf16.h>
#include <cstdint>

#define N_NODES 50000
#define N_EDGES 800000
#define IN_DIM  128
#define HID_DIM 128
#define OUT_DIM 64

#define SCAN_BS   512
#define SCAN_NB   ((N_NODES + SCAN_BS - 1) / SCAN_BS)   // 98

// ---------------- scratch (device globals: no allocation allowed) -------------
// Only referenced from DEVICE code (host-side use of __device__ symbols gives
// the host shadow address -> silent ATS writes to host RAM; R5 bug).
__device__ __align__(16) int                g_degi    [N_NODES];
__device__ __align__(16) float              g_dinv    [N_NODES];
__device__ __align__(16) int                g_rowstart[N_NODES + 1];
__device__ __align__(16) int                g_pos     [N_NODES];
__device__ __align__(16) int                g_csr     [N_EDGES];   // src per CSR slot
__device__ __align__(16) unsigned long long g_state   [SCAN_NB];   // lookback states
__device__ __align__(16) float              g_xw      [N_NODES * HID_DIM];  // x@W1 (unscaled)
__device__ __align__(16) float              g_h       [N_NODES * HID_DIM];  // layer-1 out
__device__ __align__(16) float              g_hw      [N_NODES * OUT_DIM];  // (h@W2)*dinv

// ---------------- packed f32x2 helpers -----------------------------------------
__device__ __forceinline__ unsigned long long pack2(float lo, float hi) {
    unsigned long long r;
    asm("mov.b64 %0, {%1, %2};" : "=l"(r)
        : "r"(__float_as_uint(lo)), "r"(__float_as_uint(hi)));
    return r;
}
__device__ __forceinline__ void unpack2(unsigned long long v, float& lo, float& hi) {
    unsigned a, b;
    asm("mov.b64 {%0, %1}, %2;" : "=r"(a), "=r"(b) : "l"(v));
    lo = __uint_as_float(a); hi = __uint_as_float(b);
}
__device__ __forceinline__ void ffma2(unsigned long long& d,
                                      unsigned long long a, unsigned long long b) {
    asm("fma.rn.f32x2 %0, %1, %2, %0;" : "+l"(d) : "l"(a), "l"(b));
}

// ---------------- zero: degrees + lookback states ------------------------------
__global__ void zero_kernel() {
    int i = blockIdx.x * blockDim.x + threadIdx.x;
    if (i < N_NODES) g_degi[i] = 0;
    if (i < SCAN_NB) g_state[i] = 0ull;
}

__global__ void deg_kernel(const int* __restrict__ dst) {
    int e = blockIdx.x * blockDim.x + threadIdx.x;
    if (e >= N_EDGES) return;
    unsigned d = (unsigned)dst[e];
    if (d < N_NODES) atomicAdd(&g_degi[d], 1);
}

// ---------------- single-pass scan (decoupled lookback) + fused dinv -----------
// 98 blocks <= 148 SMs: all co-resident, spin-lookback is deadlock-free.
// state[b] = flag<<32 | value ; flag: 0=invalid, 1=partial, 2=inclusive.
__global__ void scan_kernel() {
    __shared__ int sm[SCAN_BS];
    __shared__ int s_excl;
    int t = threadIdx.x, b = blockIdx.x;
    int i = b * SCAN_BS + t;
    int s = (i < N_NODES) ? g_degi[i] : 0;
    if (i < N_NODES) g_dinv[i] = rsqrtf((float)s + 1.0f);   // fused dinv
    sm[t] = s;
    __syncthreads();
    #pragma unroll
    for (int off = 1; off < SCAN_BS; off <<= 1) {
        int v = (t >= off) ? sm[t - off] : 0;
        __syncthreads();
        sm[t] += v;
        __syncthreads();
    }
    int total = sm[SCAN_BS - 1];

    if (t == 0) {
        if (b == 0) {
            atomicExch(&g_state[0], (2ull << 32) | (unsigned)total);
            s_excl = 0;
        } else {
            atomicExch(&g_state[b], (1ull << 32) | (unsigned)total);
            int excl = 0;
            int idx = b - 1;
            while (true) {
                unsigned long long st = atomicAdd(&g_state[idx], 0ull);  // atomic read
                unsigned flag = (unsigned)(st >> 32);
                if (flag == 0u) { __nanosleep(20); continue; }
                excl += (int)(unsigned)st;
                if (flag == 2u) break;
                idx--;
            }
            atomicExch(&g_state[b], (2ull << 32) | (unsigned)(excl + total));
            s_excl = excl;
        }
    }
    __syncthreads();
    if (i < N_NODES) {
        int rs = sm[t] - s + s_excl;     // exclusive prefix
        g_rowstart[i] = rs;
        g_pos[i] = rs;
    }
    if (i == 0) g_rowstart[N_NODES] = N_EDGES;
}

// ---------------- CSR fill -----------------------------------------------------
__global__ void fill_kernel(const int* __restrict__ src, const int* __restrict__ dst) {
    int e = blockIdx.x * blockDim.x + threadIdx.x;
    if (e >= N_EDGES) return;
    unsigned d = (unsigned)dst[e];
    unsigned s = (unsigned)src[e];
    if (d >= N_NODES || s >= N_NODES) return;
    int slot = atomicAdd(&g_pos[d], 1);
    g_csr[slot] = (int)s;
}

// ---------------- SGEMM: 128xBN tile, FFMA2 microkernel ------------------------
template <int BN, bool SCALE_DINV>
__device__ __forceinline__ void sgemm_body(const float* __restrict__ A,
                                           const float* __restrict__ B,
                                           float* __restrict__ C, int M) {
    constexpr int BM = 128, BK = 16, KD = 128;
    constexpr int TN = (BN == 128) ? 8 : 4;
    __shared__ float As[BK][BM];                // transposed A tile
    __shared__ float Bs[BK][BN];

    const int tid = threadIdx.x;                // 256 threads
    const int tx = tid & 15;
    const int ty = tid >> 4;
    const int row0 = blockIdx.y * BM;

    unsigned long long acc2[4][TN] = {};        // [row-pair][col]

    for (int k0 = 0; k0 < KD; k0 += BK) {
        {
            int idx = tid * 8;
            int m = idx >> 4, kk = idx & 15;    // kk in {0, 8}
            int r = row0 + m;
            float4 f0 = make_float4(0.f, 0.f, 0.f, 0.f), f1 = f0;
            if (r < M) {
                f0 = *(const float4*)&A[(size_t)r * KD + k0 + kk];
                f1 = *(const float4*)&A[(size_t)r * KD + k0 + kk + 4];
            }
            As[kk + 0][m] = f0.x; As[kk + 1][m] = f0.y;
            As[kk + 2][m] = f0.z; As[kk + 3][m] = f0.w;
            As[kk + 4][m] = f1.x; As[kk + 5][m] = f1.y;
            As[kk + 6][m] = f1.z; As[kk + 7][m] = f1.w;
        }
        if constexpr (BN == 128) {
            int idx = tid * 8;
            int kb = idx >> 7, n = idx & 127;
            const float* bp = &B[(size_t)(k0 + kb) * BN + n];
            *(float4*)&Bs[kb][n]     = *(const float4*)bp;
            *(float4*)&Bs[kb][n + 4] = *(const float4*)(bp + 4);
        } else {
            int idx = tid * 4;
            int kb = idx >> 6, n = idx & 63;
            *(float4*)&Bs[kb][n] = *(const float4*)&B[(size_t)(k0 + kb) * BN + n];
        }
        __syncthreads();

        #pragma unroll
        for (int k = 0; k < BK; k++) {
            float a[8];
            *(float4*)&a[0] = *(const float4*)&As[k][ty * 8];
            *(float4*)&a[4] = *(const float4*)&As[k][ty * 8 + 4];
            float b[TN];
            *(float4*)&b[0] = *(const float4*)&Bs[k][tx * 4];
            if constexpr (BN == 128)
                *(float4*)&b[4] = *(const float4*)&Bs[k][64 + tx * 4];

            unsigned long long a2[4];
            #pragma unroll
            for (int p = 0; p < 4; p++) a2[p] = pack2(a[2 * p], a[2 * p + 1]);
            unsigned long long b2[TN];
            #pragma unroll
            for (int j = 0; j < TN; j++) b2[j] = pack2(b[j], b[j]);

            #pragma unroll
            for (int p = 0; p < 4; p++)
                #pragma unroll
                for (int j = 0; j < TN; j++)
                    ffma2(acc2[p][j], a2[p], b2[j]);
        }
        __syncthreads();
    }

    #pragma unroll
    for (int p = 0; p < 4; p++) {
        int r0 = row0 + ty * 8 + 2 * p;
        if (r0 >= M) continue;
        float s0 = 1.f, s1 = 1.f;
        if constexpr (SCALE_DINV) {
            s0 = g_dinv[r0];
            s1 = (r0 + 1 < M) ? g_dinv[r0 + 1] : 0.f;
        }
        float v0[TN], v1[TN];
        #pragma unroll
        for (int j = 0; j < TN; j++) {
            float lo, hi;
            unpack2(acc2[p][j], lo, hi);
            v0[j] = lo * s0; v1[j] = hi * s1;
        }
        *(float4*)&C[(size_t)r0 * BN + tx * 4] = *(float4*)&v0[0];
        if (r0 + 1 < M)
            *(float4*)&C[(size_t)(r0 + 1) * BN + tx * 4] = *(float4*)&v1[0];
        if constexpr (BN == 128) {
            *(float4*)&C[(size_t)r0 * BN + 64 + tx * 4] = *(float4*)&v0[4];
            if (r0 + 1 < M)
                *(float4*)&C[(size_t)(r0 + 1) * BN + 64 + tx * 4] = *(float4*)&v1[4];
        }
    }
}

__global__ void gemm1_kernel(const float* __restrict__ x, const float* __restrict__ W1) {
    sgemm_body<HID_DIM, false>(x, W1, g_xw, N_NODES);   // unscaled: no dinv dep
}
__global__ void gemm2_kernel(const float* __restrict__ W2) {
    sgemm_body<OUT_DIM, true>(g_h, W2, g_hw, N_NODES);
}

// ---------------- gather layer 1: warp per node, 8x unrolled, per-edge dinv ----
// h[d] = relu( dinv[d] * ( sum_s xw[s]*dinv[s] + xw[d]*dinv[d] ) + b1 )
__global__ void gather1_kernel(const float* __restrict__ b1) {
    int w = (blockIdx.x * blockDim.x + threadIdx.x) >> 5;
    int lane = threadIdx.x & 31;
    if (w >= N_NODES) return;
    int beg = g_rowstart[w];
    int end = g_rowstart[w + 1];
    const float4* xw4 = reinterpret_cast<const float4*>(g_xw);

    float dself = g_dinv[w];
    float4 self = xw4[(size_t)w * 32 + lane];
    float4 acc;
    acc.x = self.x * dself; acc.y = self.y * dself;
    acc.z = self.z * dself; acc.w = self.w * dself;

    int e = beg;
    for (; e + 7 < end; e += 8) {
        int sI[8]; float dv[8]; float4 v[8];
        #pragma unroll
        for (int i = 0; i < 8; i++) sI[i] = __ldg(&g_csr[e + i]);
        #pragma unroll
        for (int i = 0; i < 8; i++) dv[i] = __ldg(&g_dinv[sI[i]]);
        #pragma unroll
        for (int i = 0; i < 8; i++) v[i] = __ldg(&xw4[(size_t)sI[i] * 32 + lane]);
        #pragma unroll
        for (int i = 0; i < 8; i++) {
            acc.x = fmaf(v[i].x, dv[i], acc.x);
            acc.y = fmaf(v[i].y, dv[i], acc.y);
            acc.z = fmaf(v[i].z, dv[i], acc.z);
            acc.w = fmaf(v[i].w, dv[i], acc.w);
        }
    }
    for (; e < end; e++) {
        int s0 = __ldg(&g_csr[e]);
        float d0 = __ldg(&g_dinv[s0]);
        float4 v0 = __ldg(&xw4[(size_t)s0 * 32 + lane]);
        acc.x = fmaf(v0.x, d0, acc.x); acc.y = fmaf(v0.y, d0, acc.y);
        acc.z = fmaf(v0.z, d0, acc.z); acc.w = fmaf(v0.w, d0, acc.w);
    }
    float4 bb = reinterpret_cast<const float4*>(b1)[lane];
    float4 r;
    r.x = fmaxf(fmaf(dself, acc.x, bb.x), 0.f);
    r.y = fmaxf(fmaf(dself, acc.y, bb.y), 0.f);
    r.z = fmaxf(fmaf(dself, acc.z, bb.z), 0.f);
    r.w = fmaxf(fmaf(dself, acc.w, bb.w), 0.f);
    reinterpret_cast<float4*>(g_h)[(size_t)w * 32 + lane] = r;
}

// ---------------- gather layer 2 + FC + leaky, fully fused, 8x unrolled --------
__global__ void gather2_kernel(const float* __restrict__ b2,
                               const float* __restrict__ Wfc,
                               const float* __restrict__ bfc,
                               float* __restrict__ out) {
    int w = (blockIdx.x * blockDim.x + threadIdx.x) >> 5;
    int lane = threadIdx.x & 31;
    if (w >= N_NODES) return;
    int beg = g_rowstart[w];
    int end = g_rowstart[w + 1];
    const float2* hw2 = reinterpret_cast<const float2*>(g_hw);   // 32 float2/row

    float2 acc = hw2[(size_t)w * 32 + lane];    // self term (hw' already scaled)
    int e = beg;
    for (; e + 7 < end; e += 8) {
        int sI[8]; float2 v[8];
        #pragma unroll
        for (int i = 0; i < 8; i++) sI[i] = __ldg(&g_csr[e + i]);
        #pragma unroll
        for (int i = 0; i < 8; i++) v[i] = __ldg(&hw2[(size_t)sI[i] * 32 + lane]);
        #pragma unroll
        for (int i = 0; i < 8; i++) { acc.x += v[i].x; acc.y += v[i].y; }
    }
    for (; e < end; e++) {
        int s0 = __ldg(&g_csr[e]);
        float2 v0 = __ldg(&hw2[(size_t)s0 * 32 + lane]);
        acc.x += v0.x; acc.y += v0.y;
    }
    float di = g_dinv[w];
    float2 b2v = reinterpret_cast<const float2*>(b2)[lane];
    float vx = di * acc.x + b2v.x;              // feature 2*lane
    float vy = di * acc.y + b2v.y;              // feature 2*lane+1

    int f0 = 2 * lane, f1 = 2 * lane + 1;
    float p0 = vx * __ldg(&Wfc[f0 * 2 + 0]) + vy * __ldg(&Wfc[f1 * 2 + 0]);
    float p1 = vx * __ldg(&Wfc[f0 * 2 + 1]) + vy * __ldg(&Wfc[f1 * 2 + 1]);
    #pragma unroll
    for (int off = 16; off > 0; off >>= 1) {
        p0 += __shfl_xor_sync(0xffffffff, p0, off);
        p1 += __shfl_xor_sync(0xffffffff, p1, off);
    }
    if (lane == 0) {
        float o0 = p0 + __ldg(&bfc[0]);
        float o1 = p1 + __ldg(&bfc[1]);
        out[w * 2 + 0] = (o0 > 0.f) ? o0 : 0.01f * o0;
        out[w * 2 + 1] = (o1 > 0.f) ? o1 : 0.01f * o1;
    }
}

// ---------------- launch -------------------------------------------------------
// Fork-join: gemm1 (stream 0) overlaps the degree/CSR chain (side stream).
extern "C" void kernel_launch(void* const* d_in, const int* in_sizes, int n_in,
                              void* d_out, int out_size) {
    const float* x   = (const float*)d_in[0];
    const int*   ei  = (const int*)d_in[1];   // JAX default: int64 demoted to int32
    const float* W1  = (const float*)d_in[2];
    const float* b1  = (const float*)d_in[3];
    const float* W2  = (const float*)d_in[4];
    const float* b2  = (const float*)d_in[5];
    const float* Wfc = (const float*)d_in[6];
    const float* bfc = (const float*)d_in[7];
    float* out = (float*)d_out;

    const int* src = ei;
    const int* dst = ei + N_EDGES;

    static cudaStream_t s_side = nullptr;
    static cudaEvent_t  e_fork = nullptr, e_join = nullptr;
    if (s_side == nullptr) {
        cudaStreamCreateWithFlags(&s_side, cudaStreamNonBlocking);
        cudaEventCreateWithFlags(&e_fork, cudaEventDisableTiming);
        cudaEventCreateWithFlags(&e_join, cudaEventDisableTiming);
    }

    // fork side stream off the (captured) default stream
    cudaEventRecord(e_fork, 0);
    cudaStreamWaitEvent(s_side, e_fork, 0);

    // side stream: degree + dinv + CSR build (4 launches)
    zero_kernel<<<(N_NODES + 255) / 256, 256, 0, s_side>>>();
    deg_kernel<<<(N_EDGES + 255) / 256, 256, 0, s_side>>>(dst);
    scan_kernel<<<SCAN_NB, SCAN_BS, 0, s_side>>>();   // single-pass + dinv
    fill_kernel<<<(N_EDGES + 255) / 256, 256, 0, s_side>>>(src, dst);
    cudaEventRecord(e_join, s_side);

    // default stream: gemm1 (independent of degree chain), then join
    gemm1_kernel<<<dim3(1, (N_NODES + 127) / 128), 256>>>(x, W1);
    cudaStreamWaitEvent(0, e_join, 0);

    // layer 1 aggregation (needs CSR + dinv + xw)
    gather1_kernel<<<(N_NODES * 32 + 255) / 256, 256>>>(b1);

    // layer 2 fused with FC + leaky relu
    gemm2_kernel<<<dim3(1, (N_NODES + 127) / 128), 256>>>(W2);
    gather2_kernel<<<(N_NODES * 32 + 255) / 256, 256>>>(b2, Wfc, bfc, out);
}